// round 16
// baseline (speedup 1.0000x reference)
#include <cuda_runtime.h>

#define B        1024
#define NUM_VARS 2048
#define LEAVES   4096
#define LEVELS   12
#define WIDTH    4096
#define NINT     (LEVELS * WIDTH)          // 49152
#define TOTAL    (LEAVES + NINT)           // 53248

#define NTHR     512
#define BBK      8                  // batch columns per block
#define NBLK     (B / BBK)          // 128 blocks
#define NDISC    384                // discovery threads (warps 0-11)

#define PCAP     1536               // max plan nodes on the fast path
#define HSZ      4096               // hash slots (power of two)
#define PROBE_MAX 256               // hash probe cap -> sFail (no hangs)
#define VPAD     9                  // val stride (9 coprime 32 -> conflict-free)
#define XPAD     2052               // floats; 8208 B row stride (16B aligned)

// Dense-fallback value buffer (touched only if plan exceeds PCAP / hash fills).
__device__ float g_dense[(size_t)NINT * B];

// ---- smem layout (bytes), 16B alignment where needed ----
#define SM_PCH   0                               // int4[PCAP]   raw children  24576
#define SM_SCH   (SM_PCH + PCAP * 16)            // int4[PCAP]   packed plan   24576
#define SM_XROW  (SM_SCH + PCAP * 16)            // float[8*XPAD]              65664
#define SM_VAL   (SM_XROW + BBK * XPAD * 4)      // float[PCAP*VPAD]           55296
#define SM_HKEY  (SM_VAL + PCAP * VPAD * 4)      // int[HSZ]                   16384
#define SM_PORIG (SM_HKEY + HSZ * 4)             // int[PCAP]                   6144
#define SM_META  (SM_PORIG + PCAP * 4)           // int[PCAP] level<<16|rank    6144
#define SM_HVAL  (SM_META + PCAP * 4)            // ushort[HSZ]                 8192
#define SM_POP   (SM_HVAL + HSZ * 2)             // uchar[PCAP]                 1536
#define SM_FLAG  (SM_POP + PCAP)                 // uchar[PCAP] expanded?       1536
#define SM_TOTAL (SM_FLAG + PCAP)                // 210,048 B

#define BAR1() asm volatile("bar.sync 1, %0;" :: "n"(NDISC) : "memory")

__global__ void __launch_bounds__(NTHR, 1)
eval_all(const float* __restrict__ x,
         const int*   __restrict__ child_idx,
         const int*   __restrict__ op_type,
         float*       __restrict__ out)
{
    extern __shared__ unsigned char sm[];
    int4*           pch   = (int4*)          (sm + SM_PCH);
    int4*           sch   = (int4*)          (sm + SM_SCH);
    float*          xrow  = (float*)         (sm + SM_XROW);
    float*          val   = (float*)         (sm + SM_VAL);
    int*            hkey  = (int*)           (sm + SM_HKEY);
    int*            porig = (int*)           (sm + SM_PORIG);
    int*            meta  = (int*)           (sm + SM_META);
    unsigned short* hval  = (unsigned short*)(sm + SM_HVAL);
    unsigned char*  pop   = (unsigned char*) (sm + SM_POP);
    unsigned char*  flag  = (unsigned char*) (sm + SM_FLAG);

    __shared__ int scnt, sFail, sNPh;
    __shared__ int slcnt[LEVELS], soff[LEVELS + 1];
    __shared__ int sMaxDep[LEVELS];              // max internal-child level per level
    __shared__ int sP[LEVELS + 1];               // phase boundaries (entry idx)

    const int tid = threadIdx.x;
    const int blk = blockIdx.x;

    // claim helper (macro to keep it identical at both depth sites):
    // claims node c (internal, raw id); on new claim sets *outCid >= 0.
#define CLAIM(c, l2, fl, outCid) do {                                         \
        int _cid = -1;                                                        \
        unsigned _slot = ((unsigned)(c) * 2654435761u) & (HSZ - 1);           \
        int _pr = 0;                                                          \
        while (true) {                                                        \
            const int _old = atomicCAS(&hkey[_slot], -1, (c));                \
            if (_old == -1) {                                                 \
                _cid = atomicAdd(&scnt, 1);                                   \
                if (_cid >= PCAP) { sFail = 1; _cid = -1; break; }            \
                flag[_cid] = (fl);                                            \
                porig[_cid] = (c);                                            \
                const int _r2 = atomicAdd(&slcnt[(l2)], 1);                   \
                meta[_cid] = ((l2) << 16) | _r2;                              \
                hval[_slot] = (unsigned short)_cid;                           \
                break;                                                        \
            }                                                                 \
            if (_old == (c)) break;                                           \
            _slot = (_slot + 1) & (HSZ - 1);                                  \
            if (++_pr >= PROBE_MAX) { sFail = 1; break; }                     \
        }                                                                     \
        (outCid) = _cid;                                                      \
    } while (0)

    if (tid < NDISC) {
        // ========= warps 0-11: depth-2 worklist-BFS discovery =========
        {   // vectorized hash init
            const int4 m1 = make_int4(-1, -1, -1, -1);
            for (int i = tid; i < HSZ / 4; i += NDISC) ((int4*)hkey)[i] = m1;
        }
        BAR1();
        if (tid < LEVELS) { slcnt[tid] = (tid == 11) ? 1 : 0; sMaxDep[tid] = -1; }
        if (tid == 0) {
            scnt = 1; sFail = 0;
            porig[0] = TOTAL - 1;                  // root = plan idx (cid) 0
            meta[0]  = (11 << 16) | 0;
            flag[0]  = 0;
        }
        BAR1();

        int s = 0, e = 1;
        while (s < e) {
            for (int i = s + tid; i < e; i += NDISC) {
                if (flag[i]) continue;             // inline-expanded last wave
                // ---- level-1 expansion of entry i ----
                const int ni = porig[i] - LEAVES;
                const int myLev = ni >> 12;
                const int4 ch = ((const int4*)child_idx)[ni];
                pch[i] = ch;
                pop[i] = (unsigned char)op_type[ni];
                const int cs[4] = {ch.x, ch.y, ch.z, ch.w};
                int kidCid[4], kidNi[4], nk = 0, mdep = -1;
                #pragma unroll
                for (int f = 0; f < 4; ++f) {
                    const int c = cs[f];
                    if (c < LEAVES) continue;
                    const int l2 = (c - LEAVES) >> 12;
                    if (l2 > mdep) mdep = l2;
                    int cid; CLAIM(c, l2, 1, cid);
                    if (cid >= 0) { kidCid[nk] = cid; kidNi[nk] = c - LEAVES; ++nk; }
                }
                if (mdep >= 0) atomicMax(&sMaxDep[myLev], mdep);
                // ---- level-2: inline-expand claimed children ----
                int4 cch[4];
                #pragma unroll
                for (int k = 0; k < 4; ++k)        // independent LDGs in parallel
                    if (k < nk) cch[k] = ((const int4*)child_idx)[kidNi[k]];
                #pragma unroll
                for (int k = 0; k < 4; ++k) {
                    if (k >= nk) continue;
                    const int cid = kidCid[k];
                    pch[cid] = cch[k];
                    pop[cid] = (unsigned char)op_type[kidNi[k]];
                    const int kLev = kidNi[k] >> 12;
                    const int gs[4] = {cch[k].x, cch[k].y, cch[k].z, cch[k].w};
                    int mdep2 = -1;
                    #pragma unroll
                    for (int f = 0; f < 4; ++f) {
                        const int gc = gs[f];
                        if (gc < LEAVES) continue;
                        const int l3 = (gc - LEAVES) >> 12;
                        if (l3 > mdep2) mdep2 = l3;
                        int cid2; CLAIM(gc, l3, 0, cid2);
                        (void)cid2;
                    }
                    if (mdep2 >= 0) atomicMax(&sMaxDep[kLev], mdep2);
                }
            }
            BAR1();   // wave's claims complete; scnt/sMaxDep stable
            s = e;
            const int sc = *(volatile int*)&scnt;
            e = (sc < PCAP) ? sc : PCAP;
            if (*(volatile int*)&sFail) break;
        }

        // ---- discovery tail: prefix offsets + dependency-merged phases ----
        if (tid == 0) {
            int o = 0;
            for (int l = 0; l < LEVELS; ++l) { soff[l] = o; o += slcnt[l]; }
            soff[LEVELS] = o;
            // greedy level->phase merge: level l joins phase starting at a
            // iff all its internal deps are below a (maxdep[l] < a).
            int nph = 0, a = 0;
            sP[0] = 0;
            for (int l = 1; l < LEVELS; ++l) {
                if (sMaxDep[l] >= a) { sP[++nph] = soff[l]; a = l; }
            }
            sP[++nph] = soff[LEVELS];
            sNPh = nph;
        }
    } else {
        // =============== warps 12-15: stage x rows into smem ===============
        for (int idx = tid - NDISC; idx < (BBK * NUM_VARS) / 4; idx += NTHR - NDISC) {
            const int r  = idx >> 9;                  // /512 float4 per row
            const int c4 = idx & 511;
            const float4 v =
                ((const float4*)x)[(size_t)(blk * BBK + r) * (NUM_VARS / 4) + c4];
            *(float4*)&xrow[r * XPAD + c4 * 4] = v;
        }
    }
    __syncthreads();   // join: plan metadata + xrow ready

    const int n = (*(volatile int*)&scnt < PCAP) ? scnt : PCAP;

    if (*(volatile int*)&sFail) {
        // =============== dense fallback (worst case only) ===============
        for (int l = 0; l < LEVELS; ++l) {
            for (int k = tid; k < WIDTH * BBK; k += NTHR) {
                const int w2 = k >> 3, b2 = k & 7, bg2 = blk * BBK + b2;
                const int ni = l * WIDTH + w2;
                const int4 ch = ((const int4*)child_idx)[ni];
                const int cs[4] = {ch.x, ch.y, ch.z, ch.w};
                float v[4];
                #pragma unroll
                for (int f = 0; f < 4; ++f) {
                    const int c = cs[f];
                    if (c < LEAVES) {
                        const float xv = xrow[b2 * XPAD + (c & (NUM_VARS - 1))];
                        v[f] = (c < NUM_VARS) ? xv : 1.0f - xv;
                    } else {
                        v[f] = g_dense[(size_t)(c - LEAVES) * B + bg2];
                    }
                }
                const float r = op_type[ni] ? (v[0] + v[1]) + (v[2] + v[3])
                                            : (v[0] * v[1]) * (v[2] * v[3]);
                g_dense[(size_t)ni * B + bg2] = r;
            }
            __syncthreads();
        }
        if (tid < BBK)
            out[blk * BBK + tid] = g_dense[(size_t)(NINT - 1) * B + blk * BBK + tid];
        return;
    }

    // ---- resolution: encode + scatter into level-sorted packed plan ----
    // 16-bit operand: bit15=leaf, bits0-11=leaf id or cid; op in bit14 of f0.
    // Packed entry: {f0|f1<<16, f2|f3<<16, dest cid, 0}.
    for (int i = tid; i < n; i += NTHR) {
        const int4 ch = pch[i];
        const int mt = meta[i];
        const int j  = soff[mt >> 16] + (mt & 0xFFFF);
        unsigned f[4];
        const int cs[4] = {ch.x, ch.y, ch.z, ch.w};
        #pragma unroll
        for (int q = 0; q < 4; ++q) {
            const int c = cs[q];
            if (c < LEAVES) f[q] = 0x8000u | (unsigned)c;
            else {
                unsigned slot = ((unsigned)c * 2654435761u) & (HSZ - 1);
                while (hkey[slot] != c) slot = (slot + 1) & (HSZ - 1);
                f[q] = hval[slot];
            }
        }
        f[0] |= ((unsigned)pop[i] & 1u) << 14;
        sch[j] = make_int4((int)(f[0] | (f[1] << 16)),
                           (int)(f[2] | (f[3] << 16)), i, 0);
    }
    __syncthreads();                              // plan finalized

    // ====== forward: merged dependency phases, 64 lanes x 8 columns ======
    const int lane = tid >> 3;                    // 0..63
    const int bb   = tid & 7;
    const int nph  = sNPh;

    for (int p = 0; p < nph; ++p) {
        const int s0 = sP[p], e0 = sP[p + 1];
        for (int j = s0 + lane; j < e0; j += 64) {
            const int4 e = sch[j];
            const unsigned f0 = (unsigned)e.x & 0xFFFFu;
            const unsigned f1 = (unsigned)e.x >> 16;
            const unsigned f2 = (unsigned)e.y & 0xFFFFu;
            const unsigned f3 = (unsigned)e.y >> 16;
            const int op = (f0 >> 14) & 1;
            #define FETCH(ff) (((ff) & 0x8000u)                               \
                ? (((ff) & 2048u)                                             \
                    ? 1.0f - xrow[bb * XPAD + (int)((ff) & 2047u)]            \
                    :        xrow[bb * XPAD + (int)((ff) & 2047u)])           \
                : val[(int)((ff) & 0xFFFu) * VPAD + bb])
            const float v0 = FETCH(f0 & 0x8FFFu);
            const float v1 = FETCH(f1);
            const float v2 = FETCH(f2);
            const float v3 = FETCH(f3);
            #undef FETCH
            const float r = op ? (v0 + v1) + (v2 + v3)
                               : (v0 * v1) * (v2 * v3);
            val[e.z * VPAD + bb] = r;
        }
        __syncthreads();
    }

    if (tid < BBK) out[blk * BBK + tid] = val[tid];   // root cid = 0
}

// ---------------------------------------------------------------------------
// Launch: x (f32), child_idx (i32), op_type (i32). One kernel; capturable.
// ---------------------------------------------------------------------------
extern "C" void kernel_launch(void* const* d_in, const int* in_sizes, int n_in,
                              void* d_out, int out_size) {
    const float* x         = (const float*)d_in[0];
    const int*   child_idx = (const int*)  d_in[1];
    const int*   op_type   = (const int*)  d_in[2];
    float*       out       = (float*)d_out;

    cudaFuncSetAttribute(eval_all,
                         cudaFuncAttributeMaxDynamicSharedMemorySize, SM_TOTAL);
    eval_all<<<NBLK, NTHR, SM_TOTAL>>>(x, child_idx, op_type, out);
}

// round 17
// speedup vs baseline: 1.1301x; 1.1301x over previous
#include <cuda_runtime.h>

#define B        1024
#define NUM_VARS 2048
#define LEAVES   4096
#define LEVELS   12
#define WIDTH    4096
#define NINT     (LEVELS * WIDTH)          // 49152
#define TOTAL    (LEAVES + NINT)           // 53248

#define NTHR     512
#define BBK      8                  // batch columns per block
#define NBLK     (B / BBK)          // 128 blocks
#define NDISC    384                // discovery threads (warps 0-11)

#define PCAP     1536               // max plan nodes on the fast path
#define HSZ      4096               // hash slots (power of two)
#define PROBE_MAX 256               // hash probe cap -> sFail (no hangs)
#define VPAD     9                  // val stride (9 coprime 32 -> conflict-free)
#define XPAD     2052               // floats; 8208 B row stride (16B aligned)

// Dense-fallback value buffer (touched only if plan exceeds PCAP / hash fills).
__device__ float g_dense[(size_t)NINT * B];

// ---- smem layout (bytes), 16B alignment where needed ----
#define SM_PCH   0                               // int4[PCAP]   raw children  24576
#define SM_SCH   (SM_PCH + PCAP * 16)            // int4[PCAP]   packed plan   24576
#define SM_XROW  (SM_SCH + PCAP * 16)            // float[8*XPAD]              65664
#define SM_VAL   (SM_XROW + BBK * XPAD * 4)      // float[PCAP*VPAD]           55296
#define SM_HKEY  (SM_VAL + PCAP * VPAD * 4)      // int[HSZ]                   16384
#define SM_PORIG (SM_HKEY + HSZ * 4)             // int[PCAP]                   6144
#define SM_META  (SM_PORIG + PCAP * 4)           // int[PCAP] level<<16|rank    6144
#define SM_HVAL  (SM_META + PCAP * 4)            // ushort[HSZ]                 8192
#define SM_TOTAL (SM_HVAL + HSZ * 2)             // 206,976 B

#define BAR1() asm volatile("bar.sync 1, %0;" :: "n"(NDISC) : "memory")

__global__ void __launch_bounds__(NTHR, 1)
eval_all(const float* __restrict__ x,
         const int*   __restrict__ child_idx,
         const int*   __restrict__ op_type,
         float*       __restrict__ out)
{
    extern __shared__ unsigned char sm[];
    int4*           pch   = (int4*)          (sm + SM_PCH);
    int4*           sch   = (int4*)          (sm + SM_SCH);
    float*          xrow  = (float*)         (sm + SM_XROW);
    float*          val   = (float*)         (sm + SM_VAL);
    int*            hkey  = (int*)           (sm + SM_HKEY);
    int*            porig = (int*)           (sm + SM_PORIG);
    int*            meta  = (int*)           (sm + SM_META);
    unsigned short* hval  = (unsigned short*)(sm + SM_HVAL);

    __shared__ int scnt, sFail, sNPh;
    __shared__ int slcnt[LEVELS], soff[LEVELS + 1];
    __shared__ int sMaxDep[LEVELS];              // max internal-child level per level
    __shared__ int sP[LEVELS + 1];               // phase boundaries (entry idx)

    const int tid = threadIdx.x;
    const int blk = blockIdx.x;

    if (tid < NDISC) {
        // =============== warps 0-11: worklist-BFS discovery ===============
        {   // vectorized hash init
            const int4 m1 = make_int4(-1, -1, -1, -1);
            for (int i = tid; i < HSZ / 4; i += NDISC) ((int4*)hkey)[i] = m1;
        }
        BAR1();
        if (tid < LEVELS) { slcnt[tid] = (tid == 11) ? 1 : 0; sMaxDep[tid] = -1; }
        if (tid == 0) {
            scnt = 1; sFail = 0;
            porig[0] = TOTAL - 1;                  // root = plan idx (cid) 0
            meta[0]  = (11 << 16) | 0;
        }
        BAR1();

        int s = 0, e = 1;
        while (s < e) {
            for (int i = s + tid; i < e; i += NDISC) {
                const int ni = porig[i] - LEAVES;
                const int myLev = ni >> 12;                   // / WIDTH
                const int4 ch = ((const int4*)child_idx)[ni];
                pch[i] = ch;
                const int cs[4] = {ch.x, ch.y, ch.z, ch.w};
                int mdep = -1;
                #pragma unroll
                for (int f = 0; f < 4; ++f) {
                    const int c = cs[f];
                    if (c < LEAVES) continue;
                    const int ci = c - LEAVES;
                    const int l2 = ci >> 12;
                    if (l2 > mdep) mdep = l2;
                    // hash claim: single CAS probe chain (dedupe + insert)
                    unsigned slot = ((unsigned)c * 2654435761u) & (HSZ - 1);
                    int probes = 0;
                    while (true) {
                        const int old = atomicCAS(&hkey[slot], -1, c);
                        if (old == -1) {                      // we claimed c
                            const int cid = atomicAdd(&scnt, 1);
                            if (cid >= PCAP) { sFail = 1; break; }
                            porig[cid] = c;
                            const int r2 = atomicAdd(&slcnt[l2], 1);
                            meta[cid] = (l2 << 16) | r2;
                            hval[slot] = (unsigned short)cid;
                            break;
                        }
                        if (old == c) break;                  // duplicate
                        slot = (slot + 1) & (HSZ - 1);
                        if (++probes >= PROBE_MAX) { sFail = 1; break; }
                    }
                }
                if (mdep >= 0) atomicMax(&sMaxDep[myLev], mdep);
            }
            BAR1();   // wave's claims complete; scnt/sMaxDep stable
            s = e;
            const int sc = *(volatile int*)&scnt;
            e = (sc < PCAP) ? sc : PCAP;
            if (*(volatile int*)&sFail) break;
        }

        // ---- discovery tail: prefix offsets + dependency-merged phases ----
        if (tid == 0) {
            int o = 0;
            for (int l = 0; l < LEVELS; ++l) { soff[l] = o; o += slcnt[l]; }
            soff[LEVELS] = o;
            // greedy level->phase merge: level l joins phase starting at a
            // iff all its internal deps are below a (maxdep[l] < a).
            int nph = 0, a = 0;
            sP[0] = 0;
            for (int l = 1; l < LEVELS; ++l) {
                if (sMaxDep[l] >= a) { sP[++nph] = soff[l]; a = l; }
            }
            sP[++nph] = soff[LEVELS];
            sNPh = nph;
        }
    } else {
        // =============== warps 12-15: stage x rows into smem ===============
        for (int idx = tid - NDISC; idx < (BBK * NUM_VARS) / 4; idx += NTHR - NDISC) {
            const int r  = idx >> 9;                  // /512 float4 per row
            const int c4 = idx & 511;
            const float4 v =
                ((const float4*)x)[(size_t)(blk * BBK + r) * (NUM_VARS / 4) + c4];
            *(float4*)&xrow[r * XPAD + c4 * 4] = v;
        }
    }
    __syncthreads();   // join: plan metadata + xrow ready

    const int n = (*(volatile int*)&scnt < PCAP) ? scnt : PCAP;

    if (*(volatile int*)&sFail) {
        // =============== dense fallback (worst case only) ===============
        for (int l = 0; l < LEVELS; ++l) {
            for (int k = tid; k < WIDTH * BBK; k += NTHR) {
                const int w2 = k >> 3, b2 = k & 7, bg2 = blk * BBK + b2;
                const int ni = l * WIDTH + w2;
                const int4 ch = ((const int4*)child_idx)[ni];
                const int cs[4] = {ch.x, ch.y, ch.z, ch.w};
                float v[4];
                #pragma unroll
                for (int f = 0; f < 4; ++f) {
                    const int c = cs[f];
                    if (c < LEAVES) {
                        const float xv = xrow[b2 * XPAD + (c & (NUM_VARS - 1))];
                        v[f] = (c < NUM_VARS) ? xv : 1.0f - xv;
                    } else {
                        v[f] = g_dense[(size_t)(c - LEAVES) * B + bg2];
                    }
                }
                const float r = op_type[ni] ? (v[0] + v[1]) + (v[2] + v[3])
                                            : (v[0] * v[1]) * (v[2] * v[3]);
                g_dense[(size_t)ni * B + bg2] = r;
            }
            __syncthreads();
        }
        if (tid < BBK)
            out[blk * BBK + tid] = g_dense[(size_t)(NINT - 1) * B + blk * BBK + tid];
        return;
    }

    // ---- resolution: encode + scatter into level-sorted packed plan ----
    // 16-bit operand: bit15=leaf, bits0-11=leaf id or cid; op in bit14 of f0.
    // op_type loaded HERE (block-wide parallel, L2-hot) — off the BFS chain.
    // Packed entry: {f0|f1<<16, f2|f3<<16, dest cid, 0}.
    for (int i = tid; i < n; i += NTHR) {
        const int4 ch = pch[i];
        const int mt = meta[i];
        const int j  = soff[mt >> 16] + (mt & 0xFFFF);
        const int op = op_type[porig[i] - LEAVES];
        unsigned f[4];
        const int cs[4] = {ch.x, ch.y, ch.z, ch.w};
        #pragma unroll
        for (int q = 0; q < 4; ++q) {
            const int c = cs[q];
            if (c < LEAVES) f[q] = 0x8000u | (unsigned)c;
            else {
                unsigned slot = ((unsigned)c * 2654435761u) & (HSZ - 1);
                while (hkey[slot] != c) slot = (slot + 1) & (HSZ - 1);
                f[q] = hval[slot];
            }
        }
        f[0] |= ((unsigned)op & 1u) << 14;
        sch[j] = make_int4((int)(f[0] | (f[1] << 16)),
                           (int)(f[2] | (f[3] << 16)), i, 0);
    }
    __syncthreads();                              // plan finalized

    // ====== forward: merged dependency phases, 64 lanes x 8 columns ======
    const int lane = tid >> 3;                    // 0..63
    const int bb   = tid & 7;
    const int nph  = sNPh;

    for (int p = 0; p < nph; ++p) {
        const int s0 = sP[p], e0 = sP[p + 1];
        for (int j = s0 + lane; j < e0; j += 64) {
            const int4 e = sch[j];
            const unsigned f0 = (unsigned)e.x & 0xFFFFu;
            const unsigned f1 = (unsigned)e.x >> 16;
            const unsigned f2 = (unsigned)e.y & 0xFFFFu;
            const unsigned f3 = (unsigned)e.y >> 16;
            const int op = (f0 >> 14) & 1;
            #define FETCH(ff) (((ff) & 0x8000u)                               \
                ? (((ff) & 2048u)                                             \
                    ? 1.0f - xrow[bb * XPAD + (int)((ff) & 2047u)]            \
                    :        xrow[bb * XPAD + (int)((ff) & 2047u)])           \
                : val[(int)((ff) & 0xFFFu) * VPAD + bb])
            const float v0 = FETCH(f0 & 0x8FFFu);
            const float v1 = FETCH(f1);
            const float v2 = FETCH(f2);
            const float v3 = FETCH(f3);
            #undef FETCH
            const float r = op ? (v0 + v1) + (v2 + v3)
                               : (v0 * v1) * (v2 * v3);
            val[e.z * VPAD + bb] = r;
        }
        __syncthreads();
    }

    if (tid < BBK) out[blk * BBK + tid] = val[tid];   // root cid = 0
}

// ---------------------------------------------------------------------------
// Launch: x (f32), child_idx (i32), op_type (i32). One kernel; capturable.
// ---------------------------------------------------------------------------
extern "C" void kernel_launch(void* const* d_in, const int* in_sizes, int n_in,
                              void* d_out, int out_size) {
    const float* x         = (const float*)d_in[0];
    const int*   child_idx = (const int*)  d_in[1];
    const int*   op_type   = (const int*)  d_in[2];
    float*       out       = (float*)d_out;

    cudaFuncSetAttribute(eval_all,
                         cudaFuncAttributeMaxDynamicSharedMemorySize, SM_TOTAL);
    eval_all<<<NBLK, NTHR, SM_TOTAL>>>(x, child_idx, op_type, out);
}